// round 7
// baseline (speedup 1.0000x reference)
#include <cuda_runtime.h>

#define B_TOT  8192
#define NN     82
#define HH     10
#define NOUT   5
#define TSTEPS 3
#define GB     8            // batches per block
#define BD     352          // active threads = 41*8 = 328 (2 nodes per thread)
#define NROW   12           // padded floats per (node,g) row -> 48B, 16B aligned
#define MHALF  41

// shared memory: adjacency + node states only
#define SM_ADJ   0                           // 2*NN*NN interleaved (in,out) pairs
#define SM_NODES (2*NN*NN)                   // NN*GB*NROW
#define SM_TOTAL (SM_NODES + NN*GB*NROW)

// dense weights + biases live in constant memory (broadcast-uniform reads)
__constant__ float c_w3w[200];
__constant__ float c_w4w[200];
__constant__ float c_w5w[200];
__constant__ float c_wout[100];
__constant__ float c_w3u[100];
__constant__ float c_w5u[100];
__constant__ float c_b3w[10];
__constant__ float c_b3u[10];
__constant__ float c_b4w[10];
__constant__ float c_b5w[10];
__constant__ float c_b5u[10];
__constant__ float c_bout[5];

union F4U { float4 v; unsigned long long u[2]; float f[4]; };
union F2U { unsigned long long u; float2 f; };

__device__ __forceinline__ unsigned long long pack2(float a, float b) {
    unsigned long long r;
    asm("mov.b64 %0, {%1, %2};" : "=l"(r) : "f"(a), "f"(b));
    return r;
}
__device__ __forceinline__ void fma2(unsigned long long& acc,
                                     unsigned long long a, unsigned long long b) {
    asm("fma.rn.f32x2 %0, %1, %2, %0;" : "+l"(acc) : "l"(a), "l"(b));
}
__device__ __forceinline__ float hsum2(unsigned long long p) {
    F2U u; u.u = p; return u.f.x + u.f.y;
}

__device__ __forceinline__ float sigmoid_f(float v) {
    return __fdividef(1.0f, 1.0f + __expf(-v));
}
__device__ __forceinline__ float tanh_f(float v) {
    return __fdividef(2.0f, 1.0f + __expf(-2.0f * v)) - 1.0f;
}

// load 10 floats from 16B-aligned SMEM as 5 f32x2 pairs
__device__ __forceinline__ void load10(const float* p, unsigned long long* d) {
    F4U q0, q1; F2U q2;
    q0.v = *(const float4*)(p);
    q1.v = *(const float4*)(p + 4);
    q2.f = *(const float2*)(p + 8);
    d[0] = q0.u[0]; d[1] = q0.u[1]; d[2] = q1.u[0]; d[3] = q1.u[1]; d[4] = q2.u;
}

// constant weight row (20 floats, 16B-aligned) dotted against TWO packed av sets
__device__ __forceinline__ void dot20x2c(const float* wrow,
                                         const unsigned long long* av0,
                                         const unsigned long long* av1,
                                         float& r0, float& r1) {
    unsigned long long a0 = 0ULL, a1 = 0ULL;
    #pragma unroll
    for (int q = 0; q < 5; q++) {
        F4U w_;
        w_.v = *(const float4*)(wrow + 4 * q);
        fma2(a0, w_.u[0], av0[2 * q]);
        fma2(a0, w_.u[1], av0[2 * q + 1]);
        fma2(a1, w_.u[0], av1[2 * q]);
        fma2(a1, w_.u[1], av1[2 * q + 1]);
    }
    r0 = hsum2(a0);
    r1 = hsum2(a1);
}

// constant u-row (10 floats, 8B-aligned) dotted against two packed vectors
__device__ __forceinline__ void dot10x2c(const float* urow,
                                         const unsigned long long* v0,
                                         const unsigned long long* v1,
                                         float& r0, float& r1) {
    unsigned long long a0 = 0ULL, a1 = 0ULL;
    #pragma unroll
    for (int p = 0; p < 5; p++) {
        F2U w; w.f = *(const float2*)(urow + 2 * p);
        fma2(a0, w.u, v0[p]);
        fma2(a1, w.u, v1[p]);
    }
    r0 = hsum2(a0);
    r1 = hsum2(a1);
}

// output head for one (node,batch)
__device__ __forceinline__ void out_head(const float* __restrict__ xr,
                                         const float* __restrict__ nr,
                                         float* __restrict__ op,
                                         float* __restrict__ fp)
{
    unsigned long long fnp[5], xp[5];
    load10(nr, fnp);
    #pragma unroll
    for (int p = 0; p < 5; p++) xp[p] = pack2(xr[2 * p], xr[2 * p + 1]);
    #pragma unroll
    for (int o = 0; o < NOUT; o++) {
        unsigned long long acc = 0ULL;
        #pragma unroll
        for (int q = 0; q < 5; q++) {
            F4U w_;
            w_.v = *(const float4*)(c_wout + o * 20 + 4 * q);
            unsigned long long opnd0 = (2 * q < 5)     ? fnp[2 * q]     : xp[2 * q - 5];
            unsigned long long opnd1 = (2 * q + 1 < 5) ? fnp[2 * q + 1] : xp[2 * q - 4];
            fma2(acc, w_.u[0], opnd0);
            fma2(acc, w_.u[1], opnd1);
        }
        op[o] = tanh_f(c_bout[o] + hsum2(acc));
    }
    #pragma unroll
    for (int h = 0; h < HH; h++) fp[h] = nr[h];
}

__global__ __launch_bounds__(BD, 2)
void ggnn_kernel(const float* __restrict__ x,
                 const float* __restrict__ in_adj,
                 const float* __restrict__ out_adj,
                 float* __restrict__ out0, float* __restrict__ outfn)
{
    extern __shared__ float sm[];
    const int tid = threadIdx.x;

    // ---- cooperative setup: adjacency interleave into smem (vectorized) ----
    for (int k = tid; k < (NN * NN) / 2; k += BD) {
        F2U a, b;
        a.f = *(const float2*)(in_adj  + 2 * k);
        b.f = *(const float2*)(out_adj + 2 * k);
        float4 w = make_float4(a.f.x, b.f.x, a.f.y, b.f.y);
        *(float4*)(sm + SM_ADJ + 4 * k) = w;
    }

    const int  i0  = tid >> 3;       // node tile 0: 0..40
    const int  i1  = i0 + MHALF;     // node tile 1: 41..81
    const int  g   = tid & 7;        // batch-in-block
    const bool act = (tid < MHALF * GB);
    const int  b   = blockIdx.x * GB + g;

    float* nr0 = sm + SM_NODES + (i0 * GB + g) * NROW;
    float* nr1 = sm + SM_NODES + (i1 * GB + g) * NROW;

    if (act) {
        const float* xr0 = x + ((size_t)b * NN + i0) * HH;
        const float* xr1 = x + ((size_t)b * NN + i1) * HH;
        #pragma unroll
        for (int h = 0; h < HH; h++) { nr0[h] = xr0[h]; nr1[h] = xr1[h]; }
    }
    __syncthreads();

    for (int st = 0; st < TSTEPS; st++) {
        float fnn0[HH], fnn1[HH];
        if (act) {
            // ---- aggregation for both nodes; states loaded once ----
            unsigned long long av0[HH], av1[HH];  // [0..4]=a_in, [5..9]=a_out pairs
            #pragma unroll
            for (int p = 0; p < HH; p++) { av0[p] = 0ULL; av1[p] = 0ULL; }

            const float* arow0 = sm + SM_ADJ + i0 * (2 * NN);
            const float* arow1 = sm + SM_ADJ + i1 * (2 * NN);
            const float* nbase = sm + SM_NODES + g * NROW;
            for (int j = 0; j < NN; j += 2) {
                F4U a0; a0.v = *(const float4*)(arow0 + 2 * j);
                F4U a1; a1.v = *(const float4*)(arow1 + 2 * j);
                const float* xjs = nbase + j * (GB * NROW);
                unsigned long long s0[5], s1[5];
                load10(xjs, s0);
                load10(xjs + GB * NROW, s1);
                unsigned long long t;
                t = pack2(a0.f[0], a0.f[0]);
                #pragma unroll
                for (int p = 0; p < 5; p++) fma2(av0[p], t, s0[p]);
                t = pack2(a0.f[1], a0.f[1]);
                #pragma unroll
                for (int p = 0; p < 5; p++) fma2(av0[5 + p], t, s0[p]);
                t = pack2(a0.f[2], a0.f[2]);
                #pragma unroll
                for (int p = 0; p < 5; p++) fma2(av0[p], t, s1[p]);
                t = pack2(a0.f[3], a0.f[3]);
                #pragma unroll
                for (int p = 0; p < 5; p++) fma2(av0[5 + p], t, s1[p]);

                t = pack2(a1.f[0], a1.f[0]);
                #pragma unroll
                for (int p = 0; p < 5; p++) fma2(av1[p], t, s0[p]);
                t = pack2(a1.f[1], a1.f[1]);
                #pragma unroll
                for (int p = 0; p < 5; p++) fma2(av1[5 + p], t, s0[p]);
                t = pack2(a1.f[2], a1.f[2]);
                #pragma unroll
                for (int p = 0; p < 5; p++) fma2(av1[p], t, s1[p]);
                t = pack2(a1.f[3], a1.f[3]);
                #pragma unroll
                for (int p = 0; p < 5; p++) fma2(av1[5 + p], t, s1[p]);
            }

            // ---- pass 1: u3 = w3u . fn for both nodes ----
            float u30[HH], u31[HH];
            {
                unsigned long long f0[5], f1[5];
                load10(nr0, f0);
                load10(nr1, f1);
                #pragma unroll
                for (int h = 0; h < HH; h++)
                    dot10x2c(c_w3u + h * 10, f0, f1, u30[h], u31[h]);
            }

            // ---- pass 2: z gates ----
            float zv0[HH], zv1[HH];
            #pragma unroll
            for (int h = 0; h < HH; h++) {
                float d0, d1;
                dot20x2c(c_w3w + h * 20, av0, av1, d0, d1);
                float bz = c_b3w[h] + c_b3u[h];
                zv0[h] = sigmoid_f(bz + u30[h] + d0);
                zv1[h] = sigmoid_f(bz + u31[h] + d1);
            }

            // ---- pass 3: r gates folded with fn -> rf = r * fn ----
            unsigned long long rf0[5], rf1[5];
            #pragma unroll
            for (int p = 0; p < 5; p++) {
                float da0, da1, db0, db1;
                dot20x2c(c_w4w + (2 * p) * 20,     av0, av1, da0, da1);
                dot20x2c(c_w4w + (2 * p + 1) * 20, av0, av1, db0, db1);
                float bra = c_b4w[2 * p]     + c_b3u[2 * p];      // ref bug: r reuses b3u
                float brb = c_b4w[2 * p + 1] + c_b3u[2 * p + 1];
                float ra0 = sigmoid_f(bra + u30[2 * p]     + da0);
                float rb0 = sigmoid_f(brb + u30[2 * p + 1] + db0);
                float ra1 = sigmoid_f(bra + u31[2 * p]     + da1);
                float rb1 = sigmoid_f(brb + u31[2 * p + 1] + db1);
                rf0[p] = pack2(ra0 * nr0[2 * p], rb0 * nr0[2 * p + 1]);
                rf1[p] = pack2(ra1 * nr1[2 * p], rb1 * nr1[2 * p + 1]);
            }

            // ---- pass 4: candidate h + state update ----
            #pragma unroll
            for (int h = 0; h < HH; h++) {
                float w0, w1, v0, v1;
                dot20x2c(c_w5w + h * 20, av0, av1, w0, w1);
                dot10x2c(c_w5u + h * 10, rf0, rf1, v0, v1);
                float bh = c_b5w[h] + c_b5u[h];
                float h0 = tanh_f(bh + w0 + v0);
                float h1 = tanh_f(bh + w1 + v1);
                float o0 = nr0[h], o1 = nr1[h];
                fnn0[h] = o0 + zv0[h] * (h0 - o0);
                fnn1[h] = o1 + zv1[h] * (h1 - o1);
            }
        }
        __syncthreads();   // reads of old states done
        if (act) {
            #pragma unroll
            for (int h = 0; h < HH; h++) { nr0[h] = fnn0[h]; nr1[h] = fnn1[h]; }
        }
        __syncthreads();   // new states visible
    }

    // ---- output head for both nodes ----
    if (act) {
        const size_t row0 = (size_t)b * NN + i0;
        const size_t row1 = (size_t)b * NN + i1;
        out_head(x + row0 * HH, nr0, out0 + row0 * NOUT, outfn + row0 * HH);
        out_head(x + row1 * HH, nr1, out0 + row1 * NOUT, outfn + row1 * HH);
    }
}

extern "C" void kernel_launch(void* const* d_in, const int* in_sizes, int n_in,
                              void* d_out, int out_size)
{
    const float* x       = (const float*)d_in[0];
    const float* in_adj  = (const float*)d_in[1];
    const float* out_adj = (const float*)d_in[2];

    // stage dense weights/biases into constant memory (async D2D, capturable)
    cudaMemcpyToSymbolAsync(c_w3w,  d_in[3],  200 * 4, 0, cudaMemcpyDeviceToDevice, 0);
    cudaMemcpyToSymbolAsync(c_b3w,  d_in[4],   10 * 4, 0, cudaMemcpyDeviceToDevice, 0);
    cudaMemcpyToSymbolAsync(c_w3u,  d_in[5],  100 * 4, 0, cudaMemcpyDeviceToDevice, 0);
    cudaMemcpyToSymbolAsync(c_b3u,  d_in[6],   10 * 4, 0, cudaMemcpyDeviceToDevice, 0);
    cudaMemcpyToSymbolAsync(c_w4w,  d_in[7],  200 * 4, 0, cudaMemcpyDeviceToDevice, 0);
    cudaMemcpyToSymbolAsync(c_b4w,  d_in[8],   10 * 4, 0, cudaMemcpyDeviceToDevice, 0);
    cudaMemcpyToSymbolAsync(c_w5w,  d_in[9],  200 * 4, 0, cudaMemcpyDeviceToDevice, 0);
    cudaMemcpyToSymbolAsync(c_b5w,  d_in[10],  10 * 4, 0, cudaMemcpyDeviceToDevice, 0);
    cudaMemcpyToSymbolAsync(c_w5u,  d_in[11], 100 * 4, 0, cudaMemcpyDeviceToDevice, 0);
    cudaMemcpyToSymbolAsync(c_b5u,  d_in[12],  10 * 4, 0, cudaMemcpyDeviceToDevice, 0);
    cudaMemcpyToSymbolAsync(c_wout, d_in[13], 100 * 4, 0, cudaMemcpyDeviceToDevice, 0);
    cudaMemcpyToSymbolAsync(c_bout, d_in[14],   5 * 4, 0, cudaMemcpyDeviceToDevice, 0);

    float* out0  = (float*)d_out;
    float* outfn = out0 + (size_t)B_TOT * NN * NOUT;

    const size_t smbytes = SM_TOTAL * sizeof(float);
    cudaFuncSetAttribute(ggnn_kernel,
                         cudaFuncAttributeMaxDynamicSharedMemorySize,
                         (int)smbytes);

    ggnn_kernel<<<B_TOT / GB, BD, smbytes>>>(x, in_adj, out_adj, out0, outfn);
}

// round 8
// speedup vs baseline: 1.0076x; 1.0076x over previous
#include <cuda_runtime.h>

#define B_TOT  8192
#define NN     82
#define HH     10
#define NOUT   5
#define TSTEPS 3
#define GB     4            // batches per block
#define BD     192          // active threads = 41*4 = 164 (2 nodes per thread)
#define NROW   12           // padded floats per (node,g) row -> 48B, 16B aligned
#define MHALF  41

// shared memory: adjacency + node states only
#define SM_ADJ   0                           // 2*NN*NN interleaved (in,out) pairs
#define SM_NODES (2*NN*NN)                   // NN*GB*NROW
#define SM_TOTAL (SM_NODES + NN*GB*NROW)

// dense weights + biases live in constant memory (broadcast-uniform reads)
__constant__ float c_w3w[200];
__constant__ float c_w4w[200];
__constant__ float c_w5w[200];
__constant__ float c_wout[100];
__constant__ float c_w3u[100];
__constant__ float c_w5u[100];
__constant__ float c_b3w[10];
__constant__ float c_b3u[10];
__constant__ float c_b4w[10];
__constant__ float c_b5w[10];
__constant__ float c_b5u[10];
__constant__ float c_bout[5];

union F4U { float4 v; unsigned long long u[2]; float f[4]; };
union F2U { unsigned long long u; float2 f; };

__device__ __forceinline__ unsigned long long pack2(float a, float b) {
    unsigned long long r;
    asm("mov.b64 %0, {%1, %2};" : "=l"(r) : "f"(a), "f"(b));
    return r;
}
__device__ __forceinline__ void fma2(unsigned long long& acc,
                                     unsigned long long a, unsigned long long b) {
    asm("fma.rn.f32x2 %0, %1, %2, %0;" : "+l"(acc) : "l"(a), "l"(b));
}
__device__ __forceinline__ float hsum2(unsigned long long p) {
    F2U u; u.u = p; return u.f.x + u.f.y;
}

__device__ __forceinline__ float sigmoid_f(float v) {
    return __fdividef(1.0f, 1.0f + __expf(-v));
}
__device__ __forceinline__ float tanh_f(float v) {
    return __fdividef(2.0f, 1.0f + __expf(-2.0f * v)) - 1.0f;
}

// load 10 floats from 16B-aligned SMEM as 5 f32x2 pairs
__device__ __forceinline__ void load10(const float* p, unsigned long long* d) {
    F4U q0, q1; F2U q2;
    q0.v = *(const float4*)(p);
    q1.v = *(const float4*)(p + 4);
    q2.f = *(const float2*)(p + 8);
    d[0] = q0.u[0]; d[1] = q0.u[1]; d[2] = q1.u[0]; d[3] = q1.u[1]; d[4] = q2.u;
}

// constant weight row (20 floats, 16B-aligned) dotted against TWO packed av sets
__device__ __forceinline__ void dot20x2c(const float* wrow,
                                         const unsigned long long* av0,
                                         const unsigned long long* av1,
                                         float& r0, float& r1) {
    unsigned long long a0 = 0ULL, a1 = 0ULL;
    #pragma unroll
    for (int q = 0; q < 5; q++) {
        F4U w_;
        w_.v = *(const float4*)(wrow + 4 * q);
        fma2(a0, w_.u[0], av0[2 * q]);
        fma2(a0, w_.u[1], av0[2 * q + 1]);
        fma2(a1, w_.u[0], av1[2 * q]);
        fma2(a1, w_.u[1], av1[2 * q + 1]);
    }
    r0 = hsum2(a0);
    r1 = hsum2(a1);
}

// constant u-row (10 floats, 8B-aligned) dotted against two packed vectors
__device__ __forceinline__ void dot10x2c(const float* urow,
                                         const unsigned long long* v0,
                                         const unsigned long long* v1,
                                         float& r0, float& r1) {
    unsigned long long a0 = 0ULL, a1 = 0ULL;
    #pragma unroll
    for (int p = 0; p < 5; p++) {
        F2U w; w.f = *(const float2*)(urow + 2 * p);
        fma2(a0, w.u, v0[p]);
        fma2(a1, w.u, v1[p]);
    }
    r0 = hsum2(a0);
    r1 = hsum2(a1);
}

// output head for one (node,batch)
__device__ __forceinline__ void out_head(const float* __restrict__ xr,
                                         const float* __restrict__ nr,
                                         float* __restrict__ op,
                                         float* __restrict__ fp)
{
    unsigned long long fnp[5], xp[5];
    load10(nr, fnp);
    #pragma unroll
    for (int p = 0; p < 5; p++) xp[p] = pack2(xr[2 * p], xr[2 * p + 1]);
    #pragma unroll
    for (int o = 0; o < NOUT; o++) {
        unsigned long long acc = 0ULL;
        #pragma unroll
        for (int q = 0; q < 5; q++) {
            F4U w_;
            w_.v = *(const float4*)(c_wout + o * 20 + 4 * q);
            unsigned long long opnd0 = (2 * q < 5)     ? fnp[2 * q]     : xp[2 * q - 5];
            unsigned long long opnd1 = (2 * q + 1 < 5) ? fnp[2 * q + 1] : xp[2 * q - 4];
            fma2(acc, w_.u[0], opnd0);
            fma2(acc, w_.u[1], opnd1);
        }
        op[o] = tanh_f(c_bout[o] + hsum2(acc));
    }
    #pragma unroll
    for (int h = 0; h < HH; h++) fp[h] = nr[h];
}

__global__ __launch_bounds__(BD, 3)
void ggnn_kernel(const float* __restrict__ x,
                 const float* __restrict__ in_adj,
                 const float* __restrict__ out_adj,
                 float* __restrict__ out0, float* __restrict__ outfn)
{
    extern __shared__ float sm[];
    const int tid = threadIdx.x;

    // ---- cooperative setup: adjacency interleave into smem (vectorized) ----
    for (int k = tid; k < (NN * NN) / 2; k += BD) {
        F2U a, b;
        a.f = *(const float2*)(in_adj  + 2 * k);
        b.f = *(const float2*)(out_adj + 2 * k);
        float4 w = make_float4(a.f.x, b.f.x, a.f.y, b.f.y);
        *(float4*)(sm + SM_ADJ + 4 * k) = w;
    }

    const int  i0  = tid >> 2;       // node tile 0: 0..40
    const int  i1  = i0 + MHALF;     // node tile 1: 41..81
    const int  g   = tid & 3;        // batch-in-block
    const bool act = (tid < MHALF * GB);
    const int  b   = blockIdx.x * GB + g;

    float* nr0 = sm + SM_NODES + (i0 * GB + g) * NROW;
    float* nr1 = sm + SM_NODES + (i1 * GB + g) * NROW;

    if (act) {
        const float* xr0 = x + ((size_t)b * NN + i0) * HH;
        const float* xr1 = x + ((size_t)b * NN + i1) * HH;
        #pragma unroll
        for (int h = 0; h < HH; h++) { nr0[h] = xr0[h]; nr1[h] = xr1[h]; }
    }
    __syncthreads();

    for (int st = 0; st < TSTEPS; st++) {
        float fnn0[HH], fnn1[HH];
        if (act) {
            // ---- aggregation with software-pipelined state loads ----
            unsigned long long av0[HH], av1[HH];  // [0..4]=a_in, [5..9]=a_out pairs
            #pragma unroll
            for (int p = 0; p < HH; p++) { av0[p] = 0ULL; av1[p] = 0ULL; }

            const float* arow0 = sm + SM_ADJ + i0 * (2 * NN);
            const float* arow1 = sm + SM_ADJ + i1 * (2 * NN);
            const float* nbase = sm + SM_NODES + g * NROW;

            unsigned long long s0[5], s1[5];      // current j-pair states
            load10(nbase, s0);
            load10(nbase + GB * NROW, s1);

            for (int j = 0; j < NN; j += 2) {
                F4U a0; a0.v = *(const float4*)(arow0 + 2 * j);
                F4U a1; a1.v = *(const float4*)(arow1 + 2 * j);

                // prefetch next iteration's states into separate regs
                unsigned long long t0[5], t1[5];
                if (j + 2 < NN) {
                    const float* xn = nbase + (j + 2) * (GB * NROW);
                    load10(xn, t0);
                    load10(xn + GB * NROW, t1);
                }

                unsigned long long t;
                t = pack2(a0.f[0], a0.f[0]);
                #pragma unroll
                for (int p = 0; p < 5; p++) fma2(av0[p], t, s0[p]);
                t = pack2(a0.f[1], a0.f[1]);
                #pragma unroll
                for (int p = 0; p < 5; p++) fma2(av0[5 + p], t, s0[p]);
                t = pack2(a0.f[2], a0.f[2]);
                #pragma unroll
                for (int p = 0; p < 5; p++) fma2(av0[p], t, s1[p]);
                t = pack2(a0.f[3], a0.f[3]);
                #pragma unroll
                for (int p = 0; p < 5; p++) fma2(av0[5 + p], t, s1[p]);

                t = pack2(a1.f[0], a1.f[0]);
                #pragma unroll
                for (int p = 0; p < 5; p++) fma2(av1[p], t, s0[p]);
                t = pack2(a1.f[1], a1.f[1]);
                #pragma unroll
                for (int p = 0; p < 5; p++) fma2(av1[5 + p], t, s0[p]);
                t = pack2(a1.f[2], a1.f[2]);
                #pragma unroll
                for (int p = 0; p < 5; p++) fma2(av1[p], t, s1[p]);
                t = pack2(a1.f[3], a1.f[3]);
                #pragma unroll
                for (int p = 0; p < 5; p++) fma2(av1[5 + p], t, s1[p]);

                #pragma unroll
                for (int p = 0; p < 5; p++) { s0[p] = t0[p]; s1[p] = t1[p]; }
            }

            // ---- pass 1: u3 = w3u . fn for both nodes ----
            float u30[HH], u31[HH];
            {
                unsigned long long f0[5], f1[5];
                load10(nr0, f0);
                load10(nr1, f1);
                #pragma unroll
                for (int h = 0; h < HH; h++)
                    dot10x2c(c_w3u + h * 10, f0, f1, u30[h], u31[h]);
            }

            // ---- pass 2+3 fused: z and r gates per h-pair (4 indep chains) ----
            float zv0[HH], zv1[HH];
            unsigned long long rf0[5], rf1[5];
            #pragma unroll
            for (int p = 0; p < 5; p++) {
                int ha = 2 * p, hb = 2 * p + 1;
                float za0, za1, zb0, zb1;
                float ra0d, ra1d, rb0d, rb1d;
                dot20x2c(c_w3w + ha * 20, av0, av1, za0, za1);
                dot20x2c(c_w4w + ha * 20, av0, av1, ra0d, ra1d);
                dot20x2c(c_w3w + hb * 20, av0, av1, zb0, zb1);
                dot20x2c(c_w4w + hb * 20, av0, av1, rb0d, rb1d);
                float bza = c_b3w[ha] + c_b3u[ha];
                float bzb = c_b3w[hb] + c_b3u[hb];
                float bra = c_b4w[ha] + c_b3u[ha];   // ref bug: r reuses b3u
                float brb = c_b4w[hb] + c_b3u[hb];
                zv0[ha] = sigmoid_f(bza + u30[ha] + za0);
                zv1[ha] = sigmoid_f(bza + u31[ha] + za1);
                zv0[hb] = sigmoid_f(bzb + u30[hb] + zb0);
                zv1[hb] = sigmoid_f(bzb + u31[hb] + zb1);
                float ra0 = sigmoid_f(bra + u30[ha] + ra0d);
                float ra1 = sigmoid_f(bra + u31[ha] + ra1d);
                float rb0 = sigmoid_f(brb + u30[hb] + rb0d);
                float rb1 = sigmoid_f(brb + u31[hb] + rb1d);
                rf0[p] = pack2(ra0 * nr0[ha], rb0 * nr0[hb]);
                rf1[p] = pack2(ra1 * nr1[ha], rb1 * nr1[hb]);
            }

            // ---- pass 4: candidate h + state update ----
            #pragma unroll
            for (int h = 0; h < HH; h++) {
                float w0, w1, v0, v1;
                dot20x2c(c_w5w + h * 20, av0, av1, w0, w1);
                dot10x2c(c_w5u + h * 10, rf0, rf1, v0, v1);
                float bh = c_b5w[h] + c_b5u[h];
                float h0 = tanh_f(bh + w0 + v0);
                float h1 = tanh_f(bh + w1 + v1);
                float o0 = nr0[h], o1 = nr1[h];
                fnn0[h] = o0 + zv0[h] * (h0 - o0);
                fnn1[h] = o1 + zv1[h] * (h1 - o1);
            }
        }
        __syncthreads();   // reads of old states done
        if (act) {
            #pragma unroll
            for (int h = 0; h < HH; h++) { nr0[h] = fnn0[h]; nr1[h] = fnn1[h]; }
        }
        __syncthreads();   // new states visible
    }

    // ---- output head for both nodes ----
    if (act) {
        const size_t row0 = (size_t)b * NN + i0;
        const size_t row1 = (size_t)b * NN + i1;
        out_head(x + row0 * HH, nr0, out0 + row0 * NOUT, outfn + row0 * HH);
        out_head(x + row1 * HH, nr1, out0 + row1 * NOUT, outfn + row1 * HH);
    }
}

extern "C" void kernel_launch(void* const* d_in, const int* in_sizes, int n_in,
                              void* d_out, int out_size)
{
    const float* x       = (const float*)d_in[0];
    const float* in_adj  = (const float*)d_in[1];
    const float* out_adj = (const float*)d_in[2];

    // stage dense weights/biases into constant memory (async D2D, capturable)
    cudaMemcpyToSymbolAsync(c_w3w,  d_in[3],  200 * 4, 0, cudaMemcpyDeviceToDevice, 0);
    cudaMemcpyToSymbolAsync(c_b3w,  d_in[4],   10 * 4, 0, cudaMemcpyDeviceToDevice, 0);
    cudaMemcpyToSymbolAsync(c_w3u,  d_in[5],  100 * 4, 0, cudaMemcpyDeviceToDevice, 0);
    cudaMemcpyToSymbolAsync(c_b3u,  d_in[6],   10 * 4, 0, cudaMemcpyDeviceToDevice, 0);
    cudaMemcpyToSymbolAsync(c_w4w,  d_in[7],  200 * 4, 0, cudaMemcpyDeviceToDevice, 0);
    cudaMemcpyToSymbolAsync(c_b4w,  d_in[8],   10 * 4, 0, cudaMemcpyDeviceToDevice, 0);
    cudaMemcpyToSymbolAsync(c_w5w,  d_in[9],  200 * 4, 0, cudaMemcpyDeviceToDevice, 0);
    cudaMemcpyToSymbolAsync(c_b5w,  d_in[10],  10 * 4, 0, cudaMemcpyDeviceToDevice, 0);
    cudaMemcpyToSymbolAsync(c_w5u,  d_in[11], 100 * 4, 0, cudaMemcpyDeviceToDevice, 0);
    cudaMemcpyToSymbolAsync(c_b5u,  d_in[12],  10 * 4, 0, cudaMemcpyDeviceToDevice, 0);
    cudaMemcpyToSymbolAsync(c_wout, d_in[13], 100 * 4, 0, cudaMemcpyDeviceToDevice, 0);
    cudaMemcpyToSymbolAsync(c_bout, d_in[14],   5 * 4, 0, cudaMemcpyDeviceToDevice, 0);

    float* out0  = (float*)d_out;
    float* outfn = out0 + (size_t)B_TOT * NN * NOUT;

    const size_t smbytes = SM_TOTAL * sizeof(float);
    cudaFuncSetAttribute(ggnn_kernel,
                         cudaFuncAttributeMaxDynamicSharedMemorySize,
                         (int)smbytes);

    ggnn_kernel<<<B_TOT / GB, BD, smbytes>>>(x, in_adj, out_adj, out0, outfn);
}

// round 9
// speedup vs baseline: 1.0646x; 1.0566x over previous
#include <cuda_runtime.h>

#define B_TOT  8192
#define NN     82
#define HH     10
#define NOUT   5
#define TSTEPS 3
#define GB     4            // batches per block
#define BD     192          // active threads = 41*4 = 164 (2 nodes per thread)
#define NROW   12           // padded floats per (node,g) row -> 48B, 16B aligned
#define MHALF  41

// shared memory: adjacency + node states only
#define SM_ADJ   0                           // 2*NN*NN interleaved (in,out) pairs
#define SM_NODES (2*NN*NN)                   // NN*GB*NROW
#define SM_TOTAL (SM_NODES + NN*GB*NROW)

// dense weights + biases live in constant memory (broadcast-uniform reads)
__constant__ float c_w3w[200];
__constant__ float c_w4w[200];
__constant__ float c_w5w[200];
__constant__ float c_wout[100];
__constant__ float c_w3u[100];
__constant__ float c_w5u[100];
__constant__ float c_b3w[10];
__constant__ float c_b3u[10];
__constant__ float c_b4w[10];
__constant__ float c_b5w[10];
__constant__ float c_b5u[10];
__constant__ float c_bout[5];

union F4U { float4 v; unsigned long long u[2]; float f[4]; };
union F2U { unsigned long long u; float2 f; };

__device__ __forceinline__ unsigned long long pack2(float a, float b) {
    unsigned long long r;
    asm("mov.b64 %0, {%1, %2};" : "=l"(r) : "f"(a), "f"(b));
    return r;
}
__device__ __forceinline__ void fma2(unsigned long long& acc,
                                     unsigned long long a, unsigned long long b) {
    asm("fma.rn.f32x2 %0, %1, %2, %0;" : "+l"(acc) : "l"(a), "l"(b));
}
__device__ __forceinline__ float hsum2(unsigned long long p) {
    F2U u; u.u = p; return u.f.x + u.f.y;
}

__device__ __forceinline__ float rcpa(float v) {
    float r; asm("rcp.approx.f32 %0, %1;" : "=f"(r) : "f"(v)); return r;
}
__device__ __forceinline__ float clamp25(float v) {
    return fminf(fmaxf(v, -25.f), 25.f);
}
// paired sigmoid: one RCP for two activations (product can't overflow after clamp)
__device__ __forceinline__ void sig2(float a, float b, float& sa, float& sb) {
    float ea = __expf(-clamp25(a));
    float eb = __expf(-clamp25(b));
    float da = 1.f + ea, db = 1.f + eb;
    float rd = rcpa(da * db);
    sa = db * rd;           // = 1/da
    sb = da * rd;           // = 1/db
}
// paired tanh: tanh(x) = 2/(1+e^-2x) - 1, shared RCP
__device__ __forceinline__ void tanh2(float a, float b, float& ta, float& tb) {
    float ea = __expf(-2.f * clamp25(a));
    float eb = __expf(-2.f * clamp25(b));
    float da = 1.f + ea, db = 1.f + eb;
    float rd = rcpa(da * db);
    ta = 2.f * (db * rd) - 1.f;
    tb = 2.f * (da * rd) - 1.f;
}
__device__ __forceinline__ float tanh1(float v) {
    float e = __expf(-2.f * clamp25(v));
    return 2.f * rcpa(1.f + e) - 1.f;
}

// load 10 floats from 16B-aligned SMEM as 5 f32x2 pairs
__device__ __forceinline__ void load10(const float* p, unsigned long long* d) {
    F4U q0, q1; F2U q2;
    q0.v = *(const float4*)(p);
    q1.v = *(const float4*)(p + 4);
    q2.f = *(const float2*)(p + 8);
    d[0] = q0.u[0]; d[1] = q0.u[1]; d[2] = q1.u[0]; d[3] = q1.u[1]; d[4] = q2.u;
}

// constant weight row (20 floats, 16B-aligned) dotted against TWO packed av sets
__device__ __forceinline__ void dot20x2c(const float* wrow,
                                         const unsigned long long* av0,
                                         const unsigned long long* av1,
                                         float& r0, float& r1) {
    unsigned long long a0 = 0ULL, a1 = 0ULL;
    #pragma unroll
    for (int q = 0; q < 5; q++) {
        F4U w_;
        w_.v = *(const float4*)(wrow + 4 * q);
        fma2(a0, w_.u[0], av0[2 * q]);
        fma2(a0, w_.u[1], av0[2 * q + 1]);
        fma2(a1, w_.u[0], av1[2 * q]);
        fma2(a1, w_.u[1], av1[2 * q + 1]);
    }
    r0 = hsum2(a0);
    r1 = hsum2(a1);
}

// constant u-row (10 floats, 8B-aligned) dotted against two packed vectors
__device__ __forceinline__ void dot10x2c(const float* urow,
                                         const unsigned long long* v0,
                                         const unsigned long long* v1,
                                         float& r0, float& r1) {
    unsigned long long a0 = 0ULL, a1 = 0ULL;
    #pragma unroll
    for (int p = 0; p < 5; p++) {
        F2U w; w.f = *(const float2*)(urow + 2 * p);
        fma2(a0, w.u, v0[p]);
        fma2(a1, w.u, v1[p]);
    }
    r0 = hsum2(a0);
    r1 = hsum2(a1);
}

// output head for one (node,batch)
__device__ __forceinline__ void out_head(const float* __restrict__ xr,
                                         const float* __restrict__ nr,
                                         float* __restrict__ op,
                                         float* __restrict__ fp)
{
    unsigned long long fnp[5], xp[5];
    load10(nr, fnp);
    #pragma unroll
    for (int p = 0; p < 5; p++) xp[p] = pack2(xr[2 * p], xr[2 * p + 1]);
    float pre[NOUT];
    #pragma unroll
    for (int o = 0; o < NOUT; o++) {
        unsigned long long acc = 0ULL;
        #pragma unroll
        for (int q = 0; q < 5; q++) {
            F4U w_;
            w_.v = *(const float4*)(c_wout + o * 20 + 4 * q);
            unsigned long long opnd0 = (2 * q < 5)     ? fnp[2 * q]     : xp[2 * q - 5];
            unsigned long long opnd1 = (2 * q + 1 < 5) ? fnp[2 * q + 1] : xp[2 * q - 4];
            fma2(acc, w_.u[0], opnd0);
            fma2(acc, w_.u[1], opnd1);
        }
        pre[o] = c_bout[o] + hsum2(acc);
    }
    float t0, t1, t2, t3;
    tanh2(pre[0], pre[1], t0, t1);
    tanh2(pre[2], pre[3], t2, t3);
    op[0] = t0; op[1] = t1; op[2] = t2; op[3] = t3;
    op[4] = tanh1(pre[4]);
    #pragma unroll
    for (int h = 0; h < HH; h++) fp[h] = nr[h];
}

__global__ __launch_bounds__(BD, 3)
void ggnn_kernel(const float* __restrict__ x,
                 const float* __restrict__ in_adj,
                 const float* __restrict__ out_adj,
                 float* __restrict__ out0, float* __restrict__ outfn)
{
    extern __shared__ float sm[];
    const int tid = threadIdx.x;

    // ---- cooperative setup: adjacency interleave into smem (vectorized) ----
    for (int k = tid; k < (NN * NN) / 2; k += BD) {
        F2U a, b;
        a.f = *(const float2*)(in_adj  + 2 * k);
        b.f = *(const float2*)(out_adj + 2 * k);
        float4 w = make_float4(a.f.x, b.f.x, a.f.y, b.f.y);
        *(float4*)(sm + SM_ADJ + 4 * k) = w;
    }

    const int  i0  = tid >> 2;       // node tile 0: 0..40
    const int  i1  = i0 + MHALF;     // node tile 1: 41..81
    const int  g   = tid & 3;        // batch-in-block
    const bool act = (tid < MHALF * GB);
    const int  b   = blockIdx.x * GB + g;

    float* nr0 = sm + SM_NODES + (i0 * GB + g) * NROW;
    float* nr1 = sm + SM_NODES + (i1 * GB + g) * NROW;

    if (act) {
        const float* xr0 = x + ((size_t)b * NN + i0) * HH;
        const float* xr1 = x + ((size_t)b * NN + i1) * HH;
        #pragma unroll
        for (int h = 0; h < HH; h++) { nr0[h] = xr0[h]; nr1[h] = xr1[h]; }
    }
    __syncthreads();

    for (int st = 0; st < TSTEPS; st++) {
        float fnn0[HH], fnn1[HH];
        if (act) {
            // ---- aggregation for both nodes; states loaded once (R6 loop) ----
            unsigned long long av0[HH], av1[HH];  // [0..4]=a_in, [5..9]=a_out pairs
            #pragma unroll
            for (int p = 0; p < HH; p++) { av0[p] = 0ULL; av1[p] = 0ULL; }

            const float* arow0 = sm + SM_ADJ + i0 * (2 * NN);
            const float* arow1 = sm + SM_ADJ + i1 * (2 * NN);
            const float* nbase = sm + SM_NODES + g * NROW;
            for (int j = 0; j < NN; j += 2) {
                F4U a0; a0.v = *(const float4*)(arow0 + 2 * j);
                F4U a1; a1.v = *(const float4*)(arow1 + 2 * j);
                const float* xjs = nbase + j * (GB * NROW);
                unsigned long long s0[5], s1[5];
                load10(xjs, s0);
                load10(xjs + GB * NROW, s1);
                unsigned long long t;
                t = pack2(a0.f[0], a0.f[0]);
                #pragma unroll
                for (int p = 0; p < 5; p++) fma2(av0[p], t, s0[p]);
                t = pack2(a0.f[1], a0.f[1]);
                #pragma unroll
                for (int p = 0; p < 5; p++) fma2(av0[5 + p], t, s0[p]);
                t = pack2(a0.f[2], a0.f[2]);
                #pragma unroll
                for (int p = 0; p < 5; p++) fma2(av0[p], t, s1[p]);
                t = pack2(a0.f[3], a0.f[3]);
                #pragma unroll
                for (int p = 0; p < 5; p++) fma2(av0[5 + p], t, s1[p]);

                t = pack2(a1.f[0], a1.f[0]);
                #pragma unroll
                for (int p = 0; p < 5; p++) fma2(av1[p], t, s0[p]);
                t = pack2(a1.f[1], a1.f[1]);
                #pragma unroll
                for (int p = 0; p < 5; p++) fma2(av1[5 + p], t, s0[p]);
                t = pack2(a1.f[2], a1.f[2]);
                #pragma unroll
                for (int p = 0; p < 5; p++) fma2(av1[p], t, s1[p]);
                t = pack2(a1.f[3], a1.f[3]);
                #pragma unroll
                for (int p = 0; p < 5; p++) fma2(av1[5 + p], t, s1[p]);
            }

            // ---- pass 1: u3 = w3u . fn for both nodes ----
            float u30[HH], u31[HH];
            {
                unsigned long long f0[5], f1[5];
                load10(nr0, f0);
                load10(nr1, f1);
                #pragma unroll
                for (int h = 0; h < HH; h++)
                    dot10x2c(c_w3u + h * 10, f0, f1, u30[h], u31[h]);
            }

            // ---- pass 2+3 fused: z and r gates per h-pair (4 indep chains) ----
            float zv0[HH], zv1[HH];
            unsigned long long rf0[5], rf1[5];
            #pragma unroll
            for (int p = 0; p < 5; p++) {
                int ha = 2 * p, hb = 2 * p + 1;
                float za0, za1, zb0, zb1;
                float ra0d, ra1d, rb0d, rb1d;
                dot20x2c(c_w3w + ha * 20, av0, av1, za0, za1);
                dot20x2c(c_w4w + ha * 20, av0, av1, ra0d, ra1d);
                dot20x2c(c_w3w + hb * 20, av0, av1, zb0, zb1);
                dot20x2c(c_w4w + hb * 20, av0, av1, rb0d, rb1d);
                float bza = c_b3w[ha] + c_b3u[ha];
                float bzb = c_b3w[hb] + c_b3u[hb];
                float bra = c_b4w[ha] + c_b3u[ha];   // ref bug: r reuses b3u
                float brb = c_b4w[hb] + c_b3u[hb];
                float ra0, ra1, rb0, rb1;
                sig2(bza + u30[ha] + za0, bra + u30[ha] + ra0d, zv0[ha], ra0);
                sig2(bza + u31[ha] + za1, bra + u31[ha] + ra1d, zv1[ha], ra1);
                sig2(bzb + u30[hb] + zb0, brb + u30[hb] + rb0d, zv0[hb], rb0);
                sig2(bzb + u31[hb] + zb1, brb + u31[hb] + rb1d, zv1[hb], rb1);
                rf0[p] = pack2(ra0 * nr0[ha], rb0 * nr0[hb]);
                rf1[p] = pack2(ra1 * nr1[ha], rb1 * nr1[hb]);
            }

            // ---- pass 4: candidate h + state update (tanh paired across nodes) ----
            #pragma unroll
            for (int h = 0; h < HH; h++) {
                float w0, w1, v0, v1;
                dot20x2c(c_w5w + h * 20, av0, av1, w0, w1);
                dot10x2c(c_w5u + h * 10, rf0, rf1, v0, v1);
                float bh = c_b5w[h] + c_b5u[h];
                float h0, h1;
                tanh2(bh + w0 + v0, bh + w1 + v1, h0, h1);
                float o0 = nr0[h], o1 = nr1[h];
                fnn0[h] = o0 + zv0[h] * (h0 - o0);
                fnn1[h] = o1 + zv1[h] * (h1 - o1);
            }
        }
        __syncthreads();   // reads of old states done
        if (act) {
            #pragma unroll
            for (int h = 0; h < HH; h++) { nr0[h] = fnn0[h]; nr1[h] = fnn1[h]; }
        }
        __syncthreads();   // new states visible
    }

    // ---- output head for both nodes ----
    if (act) {
        const size_t row0 = (size_t)b * NN + i0;
        const size_t row1 = (size_t)b * NN + i1;
        out_head(x + row0 * HH, nr0, out0 + row0 * NOUT, outfn + row0 * HH);
        out_head(x + row1 * HH, nr1, out0 + row1 * NOUT, outfn + row1 * HH);
    }
}

extern "C" void kernel_launch(void* const* d_in, const int* in_sizes, int n_in,
                              void* d_out, int out_size)
{
    const float* x       = (const float*)d_in[0];
    const float* in_adj  = (const float*)d_in[1];
    const float* out_adj = (const float*)d_in[2];

    // stage dense weights/biases into constant memory (async D2D, capturable)
    cudaMemcpyToSymbolAsync(c_w3w,  d_in[3],  200 * 4, 0, cudaMemcpyDeviceToDevice, 0);
    cudaMemcpyToSymbolAsync(c_b3w,  d_in[4],   10 * 4, 0, cudaMemcpyDeviceToDevice, 0);
    cudaMemcpyToSymbolAsync(c_w3u,  d_in[5],  100 * 4, 0, cudaMemcpyDeviceToDevice, 0);
    cudaMemcpyToSymbolAsync(c_b3u,  d_in[6],   10 * 4, 0, cudaMemcpyDeviceToDevice, 0);
    cudaMemcpyToSymbolAsync(c_w4w,  d_in[7],  200 * 4, 0, cudaMemcpyDeviceToDevice, 0);
    cudaMemcpyToSymbolAsync(c_b4w,  d_in[8],   10 * 4, 0, cudaMemcpyDeviceToDevice, 0);
    cudaMemcpyToSymbolAsync(c_w5w,  d_in[9],  200 * 4, 0, cudaMemcpyDeviceToDevice, 0);
    cudaMemcpyToSymbolAsync(c_b5w,  d_in[10],  10 * 4, 0, cudaMemcpyDeviceToDevice, 0);
    cudaMemcpyToSymbolAsync(c_w5u,  d_in[11], 100 * 4, 0, cudaMemcpyDeviceToDevice, 0);
    cudaMemcpyToSymbolAsync(c_b5u,  d_in[12],  10 * 4, 0, cudaMemcpyDeviceToDevice, 0);
    cudaMemcpyToSymbolAsync(c_wout, d_in[13], 100 * 4, 0, cudaMemcpyDeviceToDevice, 0);
    cudaMemcpyToSymbolAsync(c_bout, d_in[14],   5 * 4, 0, cudaMemcpyDeviceToDevice, 0);

    float* out0  = (float*)d_out;
    float* outfn = out0 + (size_t)B_TOT * NN * NOUT;

    const size_t smbytes = SM_TOTAL * sizeof(float);
    cudaFuncSetAttribute(ggnn_kernel,
                         cudaFuncAttributeMaxDynamicSharedMemorySize,
                         (int)smbytes);

    ggnn_kernel<<<B_TOT / GB, BD, smbytes>>>(x, in_adj, out_adj, out0, outfn);
}